// round 7
// baseline (speedup 1.0000x reference)
#include <cuda_runtime.h>
#include <cuda_bf16.h>
#include <cstdint>

#define N_NODES 50000
#define E_EDGES 800000
#define HDIM 64
#define CAP 128   // padded adjacency capacity (Poisson(16) tail; P(deg>=128) ~ 0)

// Scratch buffers (allocation-free rule: __device__ globals)
__device__ float g_y[N_NODES * HDIM];      // pre-aggregation features (act @ Wa)
__device__ float g_u[N_NODES * HDIM];      // post-MLP, pre-BN features
__device__ float g_stats[3 * 2 * HDIM];    // per-layer column sums / sums of squares
__device__ int   g_cnt[N_NODES];           // per-node in-degree counter
__device__ int   g_adj[(size_t)N_NODES * CAP];  // padded adjacency (src lists per dst)
__device__ int   g_is64;

// ---------------------------------------------------------------------------
// Detect edge-index dtype (block 0) + zero degree counters + zero BN stats.
// int64 with values < 2^31: every odd 32-bit word is 0. int32: random.
// ---------------------------------------------------------------------------
__global__ __launch_bounds__(256) void detect_zero_kernel(
    const unsigned int* __restrict__ w, int* __restrict__ flag,
    int* __restrict__ cnt, float* __restrict__ statsAll)
{
    int t = blockIdx.x * 256 + threadIdx.x;
    if (t < N_NODES) cnt[t] = 0;
    if (t < 3 * 2 * HDIM) statsAll[t] = 0.0f;
    if (blockIdx.x == 0) {
        __shared__ int anyNonZero;
        if (threadIdx.x == 0) anyNonZero = 0;
        __syncthreads();
        unsigned int v = w[2 * threadIdx.x + 1] | w[2 * (threadIdx.x + 256) + 1]
                       | w[2 * (threadIdx.x + 512) + 1] | w[2 * (threadIdx.x + 768) + 1];
        if (v != 0u) atomicOr(&anyNonZero, 1);
        __syncthreads();
        if (threadIdx.x == 0) *flag = anyNonZero ? 0 : 1;
    }
}

// ---------------------------------------------------------------------------
// Build padded adjacency: adj[dst][slot] = src. One pass, spread atomics.
// ---------------------------------------------------------------------------
__global__ __launch_bounds__(256) void build_kernel(
    const void* __restrict__ ei, const int* __restrict__ flag,
    int* __restrict__ cnt, int* __restrict__ adj)
{
    int e = blockIdx.x * 256 + threadIdx.x;
    if (e >= E_EDGES) return;
    int src, dst;
    if (*flag) {
        const long long* p = (const long long*)ei;
        src = (int)p[e];
        dst = (int)p[E_EDGES + e];
    } else {
        const int* p = (const int*)ei;
        src = p[e];
        dst = p[E_EDGES + e];
    }
    int slot = atomicAdd(&cnt[dst], 1);
    if (slot < CAP) adj[(size_t)dst * CAP + slot] = src;
}

// ---------------------------------------------------------------------------
// GEMM-A: y[128-tile] = f(A) @ W.
// MODE 0: f = identity (A = x, KTOT = 128)
// MODE 1: f = relu(BN(A)) using statsIn/gamma/beta (KTOT = 64)
// 256 threads, 128 rows x 64 cols tile, 8x4 per thread, FFMA2 mainloop.
// ---------------------------------------------------------------------------
template <int MODE, int KTOT>
__global__ __launch_bounds__(256) void gemmA_kernel(
    const float* __restrict__ A,
    const float* __restrict__ W,
    float* __restrict__ out,
    const float* __restrict__ statsIn,
    const float* __restrict__ gam,
    const float* __restrict__ bet)
{
    __shared__ float As[128 * 68];
    __shared__ float Bs[64 * 64];
    __shared__ float sc[64];
    __shared__ float sh[64];

    const int tid = threadIdx.x;
    const int tx = tid & 15;        // col group (4 cols)
    const int ty = tid >> 4;        // row group (8 rows)
    const int row0 = blockIdx.x * 128;

    if (MODE == 1) {
        if (tid < 64) {
            float s = statsIn[tid];
            float q = statsIn[64 + tid];
            float mean = s * (1.0f / N_NODES);
            float var = fmaxf(q * (1.0f / N_NODES) - mean * mean, 0.0f);
            float inv = rsqrtf(var + 1e-5f);
            float scal = gam[tid] * inv;
            sc[tid] = scal;
            sh[tid] = bet[tid] - mean * scal;
        }
        __syncthreads();
    }

    unsigned long long accp[8][2];
#pragma unroll
    for (int i = 0; i < 8; i++) { accp[i][0] = 0ULL; accp[i][1] = 0ULL; }

    for (int kt = 0; kt < KTOT; kt += 64) {
        // Weight tile 64x64 [k][col]
#pragma unroll
        for (int i = 0; i < 4; i++) {
            int idx = tid + 256 * i;
            reinterpret_cast<float4*>(Bs)[idx] =
                reinterpret_cast<const float4*>(W + kt * 64)[idx];
        }
        // Input tile 128 rows x 64 k
#pragma unroll
        for (int i = 0; i < 8; i++) {
            int idx = tid + 256 * i;
            int r = idx >> 4;
            int c = idx & 15;
            int gr = row0 + r;
            float4 v = make_float4(0.f, 0.f, 0.f, 0.f);
            if (gr < N_NODES) {
                float4 a = *reinterpret_cast<const float4*>(
                    A + (size_t)gr * KTOT + kt + 4 * c);
                if (MODE == 0) {
                    v = a;
                } else {
                    int k0 = 4 * c;
                    v.x = fmaxf(fmaf(a.x, sc[k0 + 0], sh[k0 + 0]), 0.f);
                    v.y = fmaxf(fmaf(a.y, sc[k0 + 1], sh[k0 + 1]), 0.f);
                    v.z = fmaxf(fmaf(a.z, sc[k0 + 2], sh[k0 + 2]), 0.f);
                    v.w = fmaxf(fmaf(a.w, sc[k0 + 3], sh[k0 + 3]), 0.f);
                }
            }
            *reinterpret_cast<float4*>(As + r * 68 + 4 * c) = v;
        }
        __syncthreads();

#pragma unroll 8
        for (int k = 0; k < 64; k++) {
            float4 b = *reinterpret_cast<const float4*>(Bs + k * 64 + 4 * tx);
            unsigned long long b01, b23;
            asm("mov.b64 %0, {%1, %2};" : "=l"(b01) : "f"(b.x), "f"(b.y));
            asm("mov.b64 %0, {%1, %2};" : "=l"(b23) : "f"(b.z), "f"(b.w));
#pragma unroll
            for (int i = 0; i < 8; i++) {
                float a = As[(8 * ty + i) * 68 + k];
                unsigned long long aa;
                asm("mov.b64 %0, {%1, %1};" : "=l"(aa) : "f"(a));
                asm("fma.rn.f32x2 %0, %1, %2, %0;"
                    : "+l"(accp[i][0]) : "l"(aa), "l"(b01));
                asm("fma.rn.f32x2 %0, %1, %2, %0;"
                    : "+l"(accp[i][1]) : "l"(aa), "l"(b23));
            }
        }
        __syncthreads();
    }

#pragma unroll
    for (int i = 0; i < 8; i++) {
        int gr = row0 + 8 * ty + i;
        if (gr < N_NODES) {
            float4 o;
            asm("mov.b64 {%0, %1}, %2;" : "=f"(o.x), "=f"(o.y) : "l"(accp[i][0]));
            asm("mov.b64 {%0, %1}, %2;" : "=f"(o.z), "=f"(o.w) : "l"(accp[i][1]));
            *reinterpret_cast<float4*>(out + (size_t)gr * HDIM + 4 * tx) = o;
        }
    }
}

// ---------------------------------------------------------------------------
// GEMM-B (fused gather): u = relu( relu((1+eps)*y + SUM_nbr y + ba) @ Wb + bb )
// Per 128-row block: gather neighbor sums into registers, apply transform,
// write smem A-tile, then FFMA2 mainloop; epilogue accumulates BN stats.
// ---------------------------------------------------------------------------
__global__ __launch_bounds__(256) void gemmB_kernel(
    const float* __restrict__ y,
    const float* __restrict__ W,
    float* __restrict__ out,
    const float* __restrict__ ba,
    const float* __restrict__ epsPtr,
    const float* __restrict__ bb,
    const int* __restrict__ cnt,
    const int* __restrict__ adj,
    float* __restrict__ statsOut)
{
    __shared__ float As[128 * 68];
    __shared__ float Bs[64 * 64];
    __shared__ float redsum[64];
    __shared__ float redsq[64];

    const int tid = threadIdx.x;
    const int tx = tid & 15;
    const int ty = tid >> 4;
    const int row0 = blockIdx.x * 128;

    if (tid < 64) { redsum[tid] = 0.0f; redsq[tid] = 0.0f; }

    // Weight tile (independent of gather; issue first)
#pragma unroll
    for (int i = 0; i < 4; i++) {
        int idx = tid + 256 * i;
        reinterpret_cast<float4*>(Bs)[idx] =
            reinterpret_cast<const float4*>(W)[idx];
    }

    const float epsv = 1.0f + __ldg(epsPtr);

    // ---- Fused gather: 2 threads per row, 32 features each ----
    {
        int r = tid >> 1;
        int half = tid & 1;
        int gr = row0 + r;
        float4 accv[8];
#pragma unroll
        for (int j = 0; j < 8; j++) accv[j] = make_float4(0.f, 0.f, 0.f, 0.f);

        if (gr < N_NODES) {
            int deg = cnt[gr];
            deg = deg < CAP ? deg : CAP;
            const int* nb = adj + (size_t)gr * CAP;
            for (int i = 0; i < deg; i++) {
                int s = nb[i];
                const float4* yp =
                    reinterpret_cast<const float4*>(y + (size_t)s * HDIM) + half * 8;
#pragma unroll
                for (int j = 0; j < 8; j++) {
                    float4 v = yp[j];
                    accv[j].x += v.x; accv[j].y += v.y;
                    accv[j].z += v.z; accv[j].w += v.w;
                }
            }
            const float4* yr =
                reinterpret_cast<const float4*>(y + (size_t)gr * HDIM) + half * 8;
            const float4* bap = reinterpret_cast<const float4*>(ba) + half * 8;
#pragma unroll
            for (int j = 0; j < 8; j++) {
                float4 a = yr[j];
                float4 b4 = bap[j];
                float4 v;
                v.x = fmaxf(fmaf(epsv, a.x, accv[j].x + b4.x), 0.f);
                v.y = fmaxf(fmaf(epsv, a.y, accv[j].y + b4.y), 0.f);
                v.z = fmaxf(fmaf(epsv, a.z, accv[j].z + b4.z), 0.f);
                v.w = fmaxf(fmaf(epsv, a.w, accv[j].w + b4.w), 0.f);
                *reinterpret_cast<float4*>(As + r * 68 + half * 32 + 4 * j) = v;
            }
        } else {
#pragma unroll
            for (int j = 0; j < 8; j++)
                *reinterpret_cast<float4*>(As + r * 68 + half * 32 + 4 * j) =
                    make_float4(0.f, 0.f, 0.f, 0.f);
        }
    }
    __syncthreads();

    // ---- Mainloop ----
    unsigned long long accp[8][2];
#pragma unroll
    for (int i = 0; i < 8; i++) { accp[i][0] = 0ULL; accp[i][1] = 0ULL; }

#pragma unroll 8
    for (int k = 0; k < 64; k++) {
        float4 b = *reinterpret_cast<const float4*>(Bs + k * 64 + 4 * tx);
        unsigned long long b01, b23;
        asm("mov.b64 %0, {%1, %2};" : "=l"(b01) : "f"(b.x), "f"(b.y));
        asm("mov.b64 %0, {%1, %2};" : "=l"(b23) : "f"(b.z), "f"(b.w));
#pragma unroll
        for (int i = 0; i < 8; i++) {
            float a = As[(8 * ty + i) * 68 + k];
            unsigned long long aa;
            asm("mov.b64 %0, {%1, %1};" : "=l"(aa) : "f"(a));
            asm("fma.rn.f32x2 %0, %1, %2, %0;"
                : "+l"(accp[i][0]) : "l"(aa), "l"(b01));
            asm("fma.rn.f32x2 %0, %1, %2, %0;"
                : "+l"(accp[i][1]) : "l"(aa), "l"(b23));
        }
    }
    __syncthreads();

    // ---- Epilogue: bias + relu + store + BN stats ----
    float4 bb4;
    bb4.x = __ldg(bb + 4 * tx + 0);
    bb4.y = __ldg(bb + 4 * tx + 1);
    bb4.z = __ldg(bb + 4 * tx + 2);
    bb4.w = __ldg(bb + 4 * tx + 3);
    float cs[4] = {0.f, 0.f, 0.f, 0.f};
    float cq[4] = {0.f, 0.f, 0.f, 0.f};
#pragma unroll
    for (int i = 0; i < 8; i++) {
        int gr = row0 + 8 * ty + i;
        if (gr < N_NODES) {
            float4 o;
            asm("mov.b64 {%0, %1}, %2;" : "=f"(o.x), "=f"(o.y) : "l"(accp[i][0]));
            asm("mov.b64 {%0, %1}, %2;" : "=f"(o.z), "=f"(o.w) : "l"(accp[i][1]));
            o.x = fmaxf(o.x + bb4.x, 0.f);
            o.y = fmaxf(o.y + bb4.y, 0.f);
            o.z = fmaxf(o.z + bb4.z, 0.f);
            o.w = fmaxf(o.w + bb4.w, 0.f);
            *reinterpret_cast<float4*>(out + (size_t)gr * HDIM + 4 * tx) = o;
            cs[0] += o.x; cq[0] += o.x * o.x;
            cs[1] += o.y; cq[1] += o.y * o.y;
            cs[2] += o.z; cq[2] += o.z * o.z;
            cs[3] += o.w; cq[3] += o.w * o.w;
        }
    }
#pragma unroll
    for (int j = 0; j < 4; j++) {
        atomicAdd(&redsum[4 * tx + j], cs[j]);
        atomicAdd(&redsq[4 * tx + j], cq[j]);
    }
    __syncthreads();
    if (tid < 64) {
        atomicAdd(statsOut + tid, redsum[tid]);
        atomicAdd(statsOut + 64 + tid, redsq[tid]);
    }
}

// ---------------------------------------------------------------------------
// Final: out = relu(BN(u)) @ lin_w + lin_b   (64 -> 10)
// ---------------------------------------------------------------------------
__global__ __launch_bounds__(256) void final_kernel(
    const float* __restrict__ u,
    const float* __restrict__ stats,
    const float* __restrict__ gam,
    const float* __restrict__ bet,
    const float* __restrict__ lw,
    const float* __restrict__ lb,
    float* __restrict__ out)
{
    __shared__ float sc[64];
    __shared__ float sh[64];
    __shared__ float Ws[64 * 10];
    __shared__ float act[64 * 65];

    const int tid = threadIdx.x;
    const int row0 = blockIdx.x * 64;

    if (tid < 64) {
        float s = stats[tid];
        float q = stats[64 + tid];
        float mean = s * (1.0f / N_NODES);
        float var = fmaxf(q * (1.0f / N_NODES) - mean * mean, 0.0f);
        float inv = rsqrtf(var + 1e-5f);
        float scal = gam[tid] * inv;
        sc[tid] = scal;
        sh[tid] = bet[tid] - mean * scal;
    }
    for (int idx = tid; idx < 640; idx += 256) Ws[idx] = lw[idx];
    __syncthreads();

#pragma unroll
    for (int i = 0; i < 4; i++) {
        int idx = tid + 256 * i;
        int r = idx >> 4;
        int c = idx & 15;
        int gr = row0 + r;
        float4 v = make_float4(0.f, 0.f, 0.f, 0.f);
        if (gr < N_NODES) {
            float4 a = *reinterpret_cast<const float4*>(u + (size_t)gr * HDIM + 4 * c);
            int k0 = 4 * c;
            v.x = fmaxf(fmaf(a.x, sc[k0 + 0], sh[k0 + 0]), 0.f);
            v.y = fmaxf(fmaf(a.y, sc[k0 + 1], sh[k0 + 1]), 0.f);
            v.z = fmaxf(fmaf(a.z, sc[k0 + 2], sh[k0 + 2]), 0.f);
            v.w = fmaxf(fmaf(a.w, sc[k0 + 3], sh[k0 + 3]), 0.f);
        }
        float* p = act + r * 65 + 4 * c;
        p[0] = v.x; p[1] = v.y; p[2] = v.z; p[3] = v.w;
    }
    __syncthreads();

    for (int idx = tid; idx < 640; idx += 256) {
        int r = idx / 10;
        int col = idx - r * 10;
        int gr = row0 + r;
        float sum = __ldg(lb + col);
        const float* ar = act + r * 65;
#pragma unroll 16
        for (int k = 0; k < 64; k++) sum = fmaf(ar[k], Ws[k * 10 + col], sum);
        if (gr < N_NODES) out[(size_t)gr * 10 + col] = sum;
    }
}

// ---------------------------------------------------------------------------
extern "C" void kernel_launch(void* const* d_in, const int* in_sizes, int n_in,
                              void* d_out, int out_size)
{
    const float* x = (const float*)d_in[0];
    const void* ei = d_in[1];

    const float* eps1 = (const float*)d_in[2];
    const float* w1a = (const float*)d_in[3];
    const float* b1a = (const float*)d_in[4];
    const float* w1b = (const float*)d_in[5];
    const float* b1b = (const float*)d_in[6];
    const float* g1  = (const float*)d_in[7];
    const float* be1 = (const float*)d_in[8];

    const float* eps2 = (const float*)d_in[9];
    const float* w2a = (const float*)d_in[10];
    const float* b2a = (const float*)d_in[11];
    const float* w2b = (const float*)d_in[12];
    const float* b2b = (const float*)d_in[13];
    const float* g2  = (const float*)d_in[14];
    const float* be2 = (const float*)d_in[15];

    const float* eps3 = (const float*)d_in[16];
    const float* w3a = (const float*)d_in[17];
    const float* b3a = (const float*)d_in[18];
    const float* w3b = (const float*)d_in[19];
    const float* b3b = (const float*)d_in[20];
    const float* g3  = (const float*)d_in[21];
    const float* be3 = (const float*)d_in[22];

    const float* lin_w = (const float*)d_in[23];
    const float* lin_b = (const float*)d_in[24];

    void *yP, *uP, *statsP, *cntP, *adjP, *flagP;
    cudaGetSymbolAddress(&yP, g_y);
    cudaGetSymbolAddress(&uP, g_u);
    cudaGetSymbolAddress(&statsP, g_stats);
    cudaGetSymbolAddress(&cntP, g_cnt);
    cudaGetSymbolAddress(&adjP, g_adj);
    cudaGetSymbolAddress(&flagP, g_is64);
    float* y = (float*)yP;
    float* u = (float*)uP;
    float* statsAll = (float*)statsP;
    int* cnt = (int*)cntP;
    int* adj = (int*)adjP;
    int* flag = (int*)flagP;

    float* stats1 = statsAll;
    float* stats2 = statsAll + 128;
    float* stats3 = statsAll + 256;

    const int gb128 = (N_NODES + 127) / 128;          // 391 tiles
    const int gb64 = (N_NODES + 63) / 64;             // 782 tiles (final)
    const int zb = (N_NODES + 255) / 256;

    // ---- Adjacency build (once per replay) ----
    detect_zero_kernel<<<zb, 256>>>((const unsigned int*)ei, flag, cnt, statsAll);
    build_kernel<<<(E_EDGES + 255) / 256, 256>>>(ei, flag, cnt, adj);

    // ---- Layer 1 ----
    gemmA_kernel<0, 128><<<gb128, 256>>>(x, w1a, y, nullptr, nullptr, nullptr);
    gemmB_kernel<<<gb128, 256>>>(y, w1b, u, b1a, eps1, b1b, cnt, adj, stats1);

    // ---- Layer 2 ----
    gemmA_kernel<1, 64><<<gb128, 256>>>(u, w2a, y, stats1, g1, be1);
    gemmB_kernel<<<gb128, 256>>>(y, w2b, u, b2a, eps2, b2b, cnt, adj, stats2);

    // ---- Layer 3 ----
    gemmA_kernel<1, 64><<<gb128, 256>>>(u, w3a, y, stats2, g2, be2);
    gemmB_kernel<<<gb128, 256>>>(y, w3b, u, b3a, eps3, b3b, cnt, adj, stats3);

    // ---- Final linear ----
    final_kernel<<<gb64, 256>>>(u, stats3, g3, be3, lin_w, lin_b, (float*)d_out);
}